// round 12
// baseline (speedup 1.0000x reference)
#include <cuda_runtime.h>
#include <cuda_bf16.h>

// One-hot: x [8,1024] int32 -> out [8,1024,32000] fp32 (1.048 GB of stores).
// Sixteenth-row blocks: grid = 131072 (16 per row), 128 threads, 500 float4
// per block = 3 full iters + 116-thread tail. Finest point on the
// granularity curve (full 141.1 -> 1/2 139.6 -> 1/4 137.0 -> 1/8 136.4/137.5
// us kernel); fine blocks self-balance through the HW work queue. Evict-
// first __stcs streaming stores; the 1.0f overwrite is done by the same
// thread that zeroed that slot (tid == o % 128), so same-thread same-address
// store ordering guarantees the final value with no fence or 2nd kernel.
//
// Roofline evidence: STG.128, STG.256, and the driver memset node all
// converge at ~7.2 TB/s (~91% of 8 TB/s spec) — the sustained pure-write
// ceiling on this part. Spec floor for 1.0486 GB is 131 us.

static constexpr int NUM_CLASS = 32000;
static constexpr int NC4       = NUM_CLASS / 4;    // 8000 float4 per row
static constexpr int ROWS      = 8 * 1024;         // 8192
static constexpr int CHUNK     = NC4 / 16;         // 500 float4 per block
static constexpr int THREADS   = 128;
static constexpr int FULL_IT   = CHUNK / THREADS;  // 3
static constexpr int TAIL      = CHUNK - FULL_IT * THREADS;  // 116

__global__ void __launch_bounds__(THREADS)
onehot_sixteenth_kernel(const int* __restrict__ x, float4* __restrict__ out)
{
    const int row = blockIdx.x >> 4;
    const int c   = blockIdx.x & 15;
    const int tid = threadIdx.x;

    const int t = __ldg(x + row);                  // broadcast; stores don't wait

    float4* p = out + (long long)row * NC4 + c * CHUNK;
    const float4 z = make_float4(0.f, 0.f, 0.f, 0.f);

#pragma unroll
    for (int i = 0; i < FULL_IT; ++i) {
        __stcs(p + i * THREADS + tid, z);          // evict-first streaming store
    }
    if (tid < TAIL) {
        __stcs(p + FULL_IT * THREADS + tid, z);
    }

    // hot-slot overwrite: offset of the hot float4 within this chunk
    const int o = (t >> 2) - c * CHUNK;
    if (o >= 0 && o < CHUNK && (o & (THREADS - 1)) == tid) {
        reinterpret_cast<float*>(p + o)[t & 3] = 1.0f;  // same thread zeroed p[o]
    }
}

extern "C" void kernel_launch(void* const* d_in, const int* in_sizes, int n_in,
                              void* d_out, int out_size)
{
    const int* x = (const int*)d_in[0];
    onehot_sixteenth_kernel<<<ROWS * 16, THREADS>>>(x, (float4*)d_out);
}